// round 11
// baseline (speedup 1.0000x reference)
#include <cuda_runtime.h>
#include <cstdint>

// Problem constants: x(8,1024,256), adj(8,1024,1024), W(256,256), a(1,4,128)
#define Bb    8
#define Nn    1024
#define Cc    256
#define Hh    4
#define Dd    64
#define Mrows (Bb*Nn)   // 8192 token rows
#define HD    (Hh*Dd)   // 256

typedef unsigned long long u64;

// Scratch (static device arrays: no allocation allowed)
__device__ __align__(16) static float g_Wx[Mrows*HD];   // 8.4 MB
__device__ __align__(16) static float g_ei[Mrows*Hh];
__device__ __align__(16) static float g_ej[Mrows*Hh];

// ---------------- packed f32x2 helpers ----------------
__device__ __forceinline__ u64 pk2(float v) {
    u64 r; unsigned u = __float_as_uint(v);
    asm("mov.b64 %0, {%1, %1};" : "=l"(r) : "r"(u));
    return r;
}
__device__ __forceinline__ void fma2(u64& c, u64 a, u64 b) {
    asm("fma.rn.f32x2 %0, %1, %2, %3;" : "=l"(c) : "l"(a), "l"(b), "l"(c));
}
__device__ __forceinline__ void cpa8(uint32_t dst, const float* src) {
    asm volatile("cp.async.ca.shared.global [%0], [%1], 8;" :: "r"(dst), "l"(src));
}

// ---------------- Kernel A: Wx = x @ W, fused e_i/e_j ----------------
// BM=128, BN=64 (== one head), BK=16, 256 threads.
// cp.async double-buffered tiles; column-paired f32x2 accumulators so both
// tiles load in natural row-major layout (no transpose needed).
// Thread (ty2 = t>>3, tx2 = t&7): rows ty2*4..+3, cols tx2*8..+7 (4 u64 pairs).
#define BM 128
#define BN 64
#define BK 16
#define AP 18   // padded A row: 16 floats + 2 (72 B -> bank stride 8, conflict-free)
#define BP 66   // padded B row: 64 floats + 2 (264 B, 8B-aligned rows)

__global__ __launch_bounds__(256) void gemm_eij_kernel(const float* __restrict__ x,
                                                       const float* __restrict__ W,
                                                       const float* __restrict__ a) {
    __shared__ __align__(16) float As[2][BM][AP];
    __shared__ __align__(16) float Bs[2][BK][BP];
    __shared__ float s_ai[Dd], s_aj[Dd];

    const int t  = threadIdx.x;
    const int bm = blockIdx.x * BM;
    const int h  = blockIdx.y;         // head
    const int bn = h * BN;

    if (t < Dd) { s_ai[t] = a[h * 2 * Dd + t]; s_aj[t] = a[h * 2 * Dd + Dd + t]; }

    const int ty2 = t >> 3;   // 0..31 -> rows ty2*4..+3
    const int tx2 = t & 7;    // 0..7  -> cols tx2*8..+7

    const uint32_t sa = (uint32_t)__cvta_generic_to_shared(&As[0][0][0]);
    const uint32_t sb = (uint32_t)__cvta_generic_to_shared(&Bs[0][0][0]);

    // --- async tile issue (A: 1024 8B chunks, B: 512 8B chunks) ---
    #define ISSUE_TILE(P, K0)                                                        \
    do {                                                                             \
        _Pragma("unroll")                                                            \
        for (int i = 0; i < 4; i++) {                                                \
            const int cid = t + 256 * i;                                             \
            const int row = cid >> 3, ch = (cid & 7) * 2;                            \
            cpa8(sa + (uint32_t)((((P) * BM + row) * AP + ch) * 4),                  \
                 x + (size_t)(bm + row) * Cc + (K0) + ch);                           \
        }                                                                            \
        _Pragma("unroll")                                                            \
        for (int i = 0; i < 2; i++) {                                                \
            const int cid = t + 256 * i;                                             \
            const int row = cid >> 5, ch = (cid & 31) * 2;                           \
            cpa8(sb + (uint32_t)((((P) * BK + row) * BP + ch) * 4),                  \
                 W + (size_t)((K0) + row) * HD + bn + ch);                           \
        }                                                                            \
        asm volatile("cp.async.commit_group;" ::: "memory");                         \
    } while (0)

    u64 acc[4][4];   // [row r][col-pair c]
#pragma unroll
    for (int i = 0; i < 4; i++)
#pragma unroll
        for (int j = 0; j < 4; j++) acc[i][j] = 0ull;

    ISSUE_TILE(0, 0);

    int p = 0;
    for (int k0 = 0; k0 < Cc; k0 += BK) {
        const bool more = (k0 + BK) < Cc;
        if (more) ISSUE_TILE(p ^ 1, k0 + BK);
        if (more) asm volatile("cp.async.wait_group 1;" ::: "memory");
        else      asm volatile("cp.async.wait_group 0;" ::: "memory");
        __syncthreads();

#pragma unroll
        for (int kk = 0; kk < BK; kk++) {
            const u64 ar0 = pk2(As[p][ty2 * 4 + 0][kk]);
            const u64 ar1 = pk2(As[p][ty2 * 4 + 1][kk]);
            const u64 ar2 = pk2(As[p][ty2 * 4 + 2][kk]);
            const u64 ar3 = pk2(As[p][ty2 * 4 + 3][kk]);
            const float* bp = &Bs[p][kk][tx2 * 8];
            const u64 b0 = *reinterpret_cast<const u64*>(bp + 0);
            const u64 b1 = *reinterpret_cast<const u64*>(bp + 2);
            const u64 b2 = *reinterpret_cast<const u64*>(bp + 4);
            const u64 b3 = *reinterpret_cast<const u64*>(bp + 6);
            fma2(acc[0][0],b0,ar0); fma2(acc[0][1],b1,ar0); fma2(acc[0][2],b2,ar0); fma2(acc[0][3],b3,ar0);
            fma2(acc[1][0],b0,ar1); fma2(acc[1][1],b1,ar1); fma2(acc[1][2],b2,ar1); fma2(acc[1][3],b3,ar1);
            fma2(acc[2][0],b0,ar2); fma2(acc[2][1],b1,ar2); fma2(acc[2][2],b2,ar2); fma2(acc[2][3],b3,ar2);
            fma2(acc[3][0],b0,ar3); fma2(acc[3][1],b1,ar3); fma2(acc[3][2],b2,ar3); fma2(acc[3][3],b3,ar3);
        }
        __syncthreads();
        p ^= 1;
    }

    // Epilogue: write Wx (STG.64 pairs) and fused per-head e_i/e_j partials.
    float pi[4], pj[4];
#pragma unroll
    for (int r = 0; r < 4; r++) {
        const int row = bm + ty2 * 4 + r;
        float si = 0.f, sj = 0.f;
#pragma unroll
        for (int c = 0; c < 4; c++) {
            const int d0 = tx2 * 8 + c * 2;
            float2 v = *reinterpret_cast<float2*>(&acc[r][c]);
            *reinterpret_cast<u64*>(&g_Wx[(size_t)row * HD + bn + d0]) = acc[r][c];
            si += v.x * s_ai[d0] + v.y * s_ai[d0 + 1];
            sj += v.x * s_aj[d0] + v.y * s_aj[d0 + 1];
        }
        pi[r] = si; pj[r] = sj;
    }
    // reduce across the 8 tx2 lanes (low 3 bits of the lane id)
#pragma unroll
    for (int o = 1; o < 8; o <<= 1) {
#pragma unroll
        for (int r = 0; r < 4; r++) {
            pi[r] += __shfl_xor_sync(0xffffffffu, pi[r], o);
            pj[r] += __shfl_xor_sync(0xffffffffu, pj[r], o);
        }
    }
    if (tx2 == 0) {
#pragma unroll
        for (int r = 0; r < 4; r++) {
            const int row = bm + ty2 * 4 + r;
            g_ei[row * Hh + h] = pi[r];
            g_ej[row * Hh + h] = pj[r];
        }
    }
    #undef ISSUE_TILE
}

// ---------------- Kernel B: sparse masked softmax + aggregation ----------------
// One block per (b, n). Deterministic compaction; single-pass exp (logits bounded,
// fp32-safe without max subtraction). Gather: LDG.128, 64 threads per neighbor row,
// 4 neighbor slots in parallel, fma2 accumulate, cross-slot smem reduce.
__global__ __launch_bounds__(256) void attn_kernel(const float* __restrict__ adj,
                                                   float* __restrict__ out) {
    __shared__ int   s_idx[Nn];
    __shared__ __align__(16) float s_w[Nn * Hh];
    __shared__ int   s_wcnt[8];
    __shared__ float s_red[8 * Hh];
    __shared__ float s_ei[Hh];
    __shared__ __align__(16) float4 s_part[3][64];

    const int t    = threadIdx.x;
    const int bid  = blockIdx.x;        // = b*1024 + n
    const int b    = bid >> 10;
    const int n    = bid & (Nn - 1);
    const int lane = t & 31;
    const int w    = t >> 5;

    if (t < Hh) s_ei[t] = g_ei[bid * Hh + t];

    // --- Phase 1: compact neighbor list (adj!=0 || j==n), sorted, no atomics ---
    const float4 av = reinterpret_cast<const float4*>(adj + (size_t)bid * Nn)[t];
    const int j0 = 4 * t;
    const int p0 = (av.x != 0.f) | (j0 == n);
    const int p1 = (av.y != 0.f) | (j0 + 1 == n);
    const int p2 = (av.z != 0.f) | (j0 + 2 == n);
    const int p3 = (av.w != 0.f) | (j0 + 3 == n);
    const int cnt = p0 + p1 + p2 + p3;
    int incl = cnt;
#pragma unroll
    for (int o = 1; o < 32; o <<= 1) {
        int v = __shfl_up_sync(0xffffffffu, incl, o);
        if (lane >= o) incl += v;
    }
    if (lane == 31) s_wcnt[w] = incl;
    __syncthreads();
    int base = 0, total = 0;
#pragma unroll
    for (int ww = 0; ww < 8; ++ww) {
        const int c = s_wcnt[ww];
        total += c;
        if (ww < w) base += c;
    }
    int off = base + incl - cnt;
    if (p0) s_idx[off++] = j0;
    if (p1) s_idx[off++] = j0 + 1;
    if (p2) s_idx[off++] = j0 + 2;
    if (p3) s_idx[off++] = j0 + 3;
    __syncthreads();

    // --- Phase 2: w = exp(leaky(ei+ej)); per-head sums; rewrite s_idx to
    //     float4-row offsets (j * 64) for the gather. ---
    const float ei0 = s_ei[0], ei1 = s_ei[1], ei2 = s_ei[2], ei3 = s_ei[3];
    float s0 = 0.f, s1 = 0.f, s2 = 0.f, s3 = 0.f;
    for (int k = t; k < total; k += 256) {
        const int j = s_idx[k];
        float4 ej = *reinterpret_cast<const float4*>(g_ej + ((size_t)(b << 10) + j) * Hh);
        float e0 = ei0 + ej.x; e0 = e0 > 0.f ? e0 : 0.2f * e0;
        float e1 = ei1 + ej.y; e1 = e1 > 0.f ? e1 : 0.2f * e1;
        float e2 = ei2 + ej.z; e2 = e2 > 0.f ? e2 : 0.2f * e2;
        float e3 = ei3 + ej.w; e3 = e3 > 0.f ? e3 : 0.2f * e3;
        e0 = __expf(e0); e1 = __expf(e1); e2 = __expf(e2); e3 = __expf(e3);
        reinterpret_cast<float4*>(s_w)[k] = make_float4(e0, e1, e2, e3);
        s0 += e0; s1 += e1; s2 += e2; s3 += e3;
        s_idx[k] = j << 6;   // float4 units: j * (HD/4)
    }
#pragma unroll
    for (int o = 16; o >= 1; o >>= 1) {
        s0 += __shfl_xor_sync(0xffffffffu, s0, o);
        s1 += __shfl_xor_sync(0xffffffffu, s1, o);
        s2 += __shfl_xor_sync(0xffffffffu, s2, o);
        s3 += __shfl_xor_sync(0xffffffffu, s3, o);
    }
    if (lane == 0) { s_red[w*4+0]=s0; s_red[w*4+1]=s1; s_red[w*4+2]=s2; s_red[w*4+3]=s3; }
    __syncthreads();

    // --- Phase 3: gather. slot = t>>6 walks neighbors k = slot, slot+4, ...;
    //     u = t&63 is the float4 channel index (head h = u>>4). ---
    const int slot = t >> 6;
    const int u    = t & 63;
    const int h    = u >> 4;

    float gsum = 0.f;
#pragma unroll
    for (int ww = 0; ww < 8; ww++) gsum += s_red[ww*4 + h];

    const float4* basep = reinterpret_cast<const float4*>(g_Wx + ((size_t)(b << 10)) * HD) + u;
    u64 aA = 0ull, aB = 0ull, aC = 0ull, aD = 0ull;
    int k = slot;
    for (; k + 4 < total; k += 8) {
        const int o0 = s_idx[k], o1 = s_idx[k + 4];
        const u64 w0 = pk2(s_w[k * 4 + h]);
        const u64 w1 = pk2(s_w[(k + 4) * 4 + h]);
        const float4 f0 = basep[o0];
        const float4 f1 = basep[o1];
        const u64* q0 = reinterpret_cast<const u64*>(&f0);
        const u64* q1 = reinterpret_cast<const u64*>(&f1);
        fma2(aA, q0[0], w0); fma2(aB, q0[1], w0);
        fma2(aC, q1[0], w1); fma2(aD, q1[1], w1);
    }
    for (; k < total; k += 4) {
        const u64 wv = pk2(s_w[k * 4 + h]);
        const float4 f = basep[s_idx[k]];
        const u64* q = reinterpret_cast<const u64*>(&f);
        fma2(aA, q[0], wv); fma2(aB, q[1], wv);
    }
    float2 vA = *reinterpret_cast<float2*>(&aA);
    float2 vB = *reinterpret_cast<float2*>(&aB);
    float2 vC = *reinterpret_cast<float2*>(&aC);
    float2 vD = *reinterpret_cast<float2*>(&aD);
    float4 part;
    part.x = vA.x + vC.x; part.y = vA.y + vC.y;
    part.z = vB.x + vD.x; part.w = vB.y + vD.y;

    if (slot > 0) s_part[slot - 1][u] = part;
    __syncthreads();
    if (slot == 0) {
        const float4 q1 = s_part[0][u];
        const float4 q2 = s_part[1][u];
        const float4 q3 = s_part[2][u];
        float4 res;
        res.x = ((part.x + q1.x) + (q2.x + q3.x)) / gsum;
        res.y = ((part.y + q1.y) + (q2.y + q3.y)) / gsum;
        res.z = ((part.z + q1.z) + (q2.z + q3.z)) / gsum;
        res.w = ((part.w + q1.w) + (q2.w + q3.w)) / gsum;
        reinterpret_cast<float4*>(out)[(size_t)bid * 64 + u] = res;
    }
}

// ---------------- launch ----------------
extern "C" void kernel_launch(void* const* d_in, const int* in_sizes, int n_in,
                              void* d_out, int out_size) {
    const float* x   = (const float*)d_in[0];  // (8,1024,256)
    const float* adj = (const float*)d_in[1];  // (8,1024,1024)
    const float* W   = (const float*)d_in[2];  // (256,256)
    const float* a   = (const float*)d_in[3];  // (1,4,128)
    float* out = (float*)d_out;                // (8,1024,256)

    (void)in_sizes; (void)n_in; (void)out_size;

    gemm_eij_kernel<<<dim3(Mrows / BM, Hh), 256>>>(x, W, a);
    attn_kernel<<<Mrows, 256>>>(adj, out);
}